// round 3
// baseline (speedup 1.0000x reference)
#include <cuda_runtime.h>

// Problem constants
#define PP 8
#define BB 256
#define NN 512
#define KK 64
#define THREADS 256

// rehebbian constants (double-precision precomputed):
// n = N * rho^2 = 512 * 0.998001 = 510.976512
// g = 0.5*(log(1+rho)-log(1-rho))/rho = 3.8040054350965846
#define G_CONST  3.8040054350965846f
#define INV_N    0.00195703687008f   // 1/510.976512

__global__ __launch_bounds__(THREADS, 8)
void ghu_kernel(const float* __restrict__ WL,
                const float* __restrict__ WR,
                const float* __restrict__ v_tm1,
                const float* __restrict__ v_t,
                const int*   __restrict__ ac_idx,
                const int*   __restrict__ pc_mask,
                float* __restrict__ out) {
    const int b = blockIdx.x;   // 0..B-1
    const int p = blockIdx.y;   // 0..P-1
    const int tid  = threadIdx.x;
    const int warp = tid >> 5;
    const int lane = tid & 31;

    const bool sel = (ac_idx[b] == p);
    const bool msk = (pc_mask[b * PP + p] != 0);

    float* out_vnext = out;                                   // [B,N]
    float* out_dWL   = out + (size_t)BB * NN;                 // [P,B,N,1]
    float* out_dWR   = out + (size_t)BB * NN + (size_t)PP * BB * NN; // [P,B,1,N]

    float* dWLrow = out_dWL + ((size_t)p * BB + b) * NN;
    float* dWRrow = out_dWR + ((size_t)p * BB + b) * NN;
    const float* vtm1_row = v_tm1 + (size_t)b * NN;
    const float* vt_row   = v_t   + (size_t)b * NN;

    // ---- dWR: needs no weight data at all ----
    if (msk) {
        for (int i = tid; i < NN; i += THREADS)
            dWRrow[i] = vtm1_row[i] * INV_N;
    } else {
        for (int i = tid; i < NN; i += THREADS)
            dWRrow[i] = 0.0f;
    }

    // Tiles with no mask and not selected: zero dWL, done. No weight reads.
    if (!msk && !sel) {
        for (int i = tid; i < NN; i += THREADS)
            dWLrow[i] = 0.0f;
        return;
    }

    __shared__ float sv_t[NN];
    __shared__ float sv_tm1[NN];
    __shared__ float sWRx[KK];
    __shared__ float sWx[KK];
    __shared__ float sAcc1[NN];   // WLWRx per n
    __shared__ float sAcc2[NN];   // WL·Wx per n (selected path)

    for (int i = tid; i < NN; i += THREADS) {
        sv_t[i]   = vt_row[i];
        sv_tm1[i] = vtm1_row[i];
    }
    __syncthreads();

    const size_t tileOff = ((size_t)p * BB + b) * (size_t)(NN * KK);
    const float* WRt = WR + tileOff;   // [K, N] row-major, N contiguous
    const float* WLt = WL + tileOff;   // [N, K] row-major, K contiguous

    // ---- Phase A: WRx[k] = WR[k,:]·v_tm1 ; Wx[k] = WR[k,:]·v_t ----
    // one warp per k-row; 512 floats = 128 float4, 4 per lane
    for (int k = warp; k < KK; k += (THREADS / 32)) {
        const float4* row = (const float4*)(WRt + (size_t)k * NN);
        float acc1 = 0.0f, acc2 = 0.0f;
        #pragma unroll
        for (int j = 0; j < 4; j++) {
            float4 w = row[lane + 32 * j];
            int base = 4 * (lane + 32 * j);
            acc1 = fmaf(w.x, sv_tm1[base+0], acc1);
            acc1 = fmaf(w.y, sv_tm1[base+1], acc1);
            acc1 = fmaf(w.z, sv_tm1[base+2], acc1);
            acc1 = fmaf(w.w, sv_tm1[base+3], acc1);
            acc2 = fmaf(w.x, sv_t[base+0], acc2);
            acc2 = fmaf(w.y, sv_t[base+1], acc2);
            acc2 = fmaf(w.z, sv_t[base+2], acc2);
            acc2 = fmaf(w.w, sv_t[base+3], acc2);
        }
        #pragma unroll
        for (int o = 16; o > 0; o >>= 1) {
            acc1 += __shfl_down_sync(0xFFFFFFFFu, acc1, o);
            acc2 += __shfl_down_sync(0xFFFFFFFFu, acc2, o);
        }
        if (lane == 0) { sWRx[k] = acc1; sWx[k] = acc2; }
    }
    __syncthreads();

    // ---- Phase B: per n: WLWRx[n] = WL[n,:]·WRx ; vpre[n] = WL[n,:]·Wx ----
    // each warp handles 2 rows via 16-lane groups; row = 64 floats = 16 float4
    {
        const int half = lane >> 4;   // 0/1 -> which of the 2 rows
        const int hl   = lane & 15;   // lane within 16-group
        const int kb   = 4 * hl;
        for (int n0 = warp * 2; n0 < NN; n0 += 2 * (THREADS / 32)) {
            int n = n0 + half;
            const float4* row = (const float4*)(WLt + (size_t)n * KK);
            float4 w = row[hl];
            float a1 = w.x * sWRx[kb+0] + w.y * sWRx[kb+1]
                     + w.z * sWRx[kb+2] + w.w * sWRx[kb+3];
            float a2 = w.x * sWx[kb+0] + w.y * sWx[kb+1]
                     + w.z * sWx[kb+2] + w.w * sWx[kb+3];
            #pragma unroll
            for (int o = 8; o > 0; o >>= 1) {
                a1 += __shfl_down_sync(0xFFFFFFFFu, a1, o, 16);
                a2 += __shfl_down_sync(0xFFFFFFFFu, a2, o, 16);
            }
            if (hl == 0) { sAcc1[n] = a1; sAcc2[n] = a2; }
        }
    }
    __syncthreads();

    // ---- Final coalesced writes ----
    if (msk) {
        for (int i = tid; i < NN; i += THREADS)
            dWLrow[i] = G_CONST * sv_t[i] - sAcc1[i];
    } else {
        for (int i = tid; i < NN; i += THREADS)
            dWLrow[i] = 0.0f;
    }
    if (sel) {
        float* vrow = out_vnext + (size_t)b * NN;
        for (int i = tid; i < NN; i += THREADS)
            vrow[i] = tanhf(sAcc2[i]);
    }
}

extern "C" void kernel_launch(void* const* d_in, const int* in_sizes, int n_in,
                              void* d_out, int out_size) {
    const float* WL    = (const float*)d_in[0];
    const float* WR    = (const float*)d_in[1];
    const float* v_tm1 = (const float*)d_in[2];
    const float* v_t   = (const float*)d_in[3];
    const int*   ac    = (const int*)d_in[4];
    const int*   pcm   = (const int*)d_in[5];
    float* out = (float*)d_out;

    dim3 grid(BB, PP);
    ghu_kernel<<<grid, THREADS>>>(WL, WR, v_tm1, v_t, ac, pcm, out);
}

// round 5
// speedup vs baseline: 1.4964x; 1.4964x over previous
#include <cuda_runtime.h>

#define PP 8
#define BB 256
#define NN 512
#define KK 64
#define THREADS 256

// n = N*rho^2 = 510.976512 ; g = 0.5*(log(1+rho)-log(1-rho))/rho
#define G_CONST  3.8040054350965846f
#define INV_N    0.00195703687008f

__global__ __launch_bounds__(THREADS, 4)
void ghu_kernel(const float* __restrict__ WL,
                const float* __restrict__ WR,
                const float* __restrict__ v_tm1,
                const float* __restrict__ v_t,
                const int*   __restrict__ ac_idx,
                const int*   __restrict__ pc_mask,
                float* __restrict__ out) {
    const int b = blockIdx.x;
    const int p = blockIdx.y;
    const int tid  = threadIdx.x;
    const int warp = tid >> 5;
    const int lane = tid & 31;

    const bool sel = (ac_idx[b] == p);
    const bool msk = (pc_mask[b * PP + p] != 0);

    float* out_vnext = out;                                    // [B,N]
    float* out_dWL   = out + (size_t)BB * NN;                  // [P,B,N,1]
    float* out_dWR   = out_dWL + (size_t)PP * BB * NN;         // [P,B,1,N]
    float* dWLrow = out_dWL + ((size_t)p * BB + b) * NN;
    float* dWRrow = out_dWR + ((size_t)p * BB + b) * NN;
    const float* vtm1_row = v_tm1 + (size_t)b * NN;
    const float* vt_row   = v_t   + (size_t)b * NN;

    // ---- dWR needs no weight data: vectorized write (128 float4) ----
    if (tid < NN / 4) {
        float4 vv = ((const float4*)vtm1_row)[tid];
        float4 o;
        if (msk) { o.x = vv.x * INV_N; o.y = vv.y * INV_N;
                   o.z = vv.z * INV_N; o.w = vv.w * INV_N; }
        else     { o = make_float4(0.f, 0.f, 0.f, 0.f); }
        ((float4*)dWRrow)[tid] = o;
    }

    // Unneeded tiles: zero dWL, done. No weight reads.
    if (!msk && !sel) {
        if (tid < NN / 4)
            ((float4*)dWLrow)[tid] = make_float4(0.f, 0.f, 0.f, 0.f);
        return;
    }

    __shared__ float sv_t[NN];
    __shared__ float sv_tm1[NN];
    __shared__ float sWRx[KK];
    __shared__ float sWx[KK];
    __shared__ float sAcc1[NN];
    __shared__ float sAcc2[NN];

    if (tid < NN / 4) {
        ((float4*)sv_t)[tid]   = ((const float4*)vt_row)[tid];
        ((float4*)sv_tm1)[tid] = ((const float4*)vtm1_row)[tid];
    }
    __syncthreads();

    const size_t tileOff = ((size_t)p * BB + b) * (size_t)(NN * KK);
    const float* WRt = WR + tileOff;   // [K, N], N contiguous
    const float* WLt = WL + tileOff;   // [N, K], K contiguous

    // ---- Phase A: WRx[k]=WR[k,:]·v_tm1 ; Wx[k]=WR[k,:]·v_t ----
    // warp handles k = warp + 8*r, r=0..7, in two passes of 4 rows.
    // Per j-iteration: 4 independent LDG.128 in flight (MLP 4/warp).
    #pragma unroll
    for (int rb = 0; rb < 2; rb++) {
        float a1[4] = {0.f, 0.f, 0.f, 0.f};
        float a2[4] = {0.f, 0.f, 0.f, 0.f};
        const float4* r0 = (const float4*)(WRt + (size_t)(warp + 8 * (4 * rb + 0)) * NN);
        const float4* r1 = (const float4*)(WRt + (size_t)(warp + 8 * (4 * rb + 1)) * NN);
        const float4* r2 = (const float4*)(WRt + (size_t)(warp + 8 * (4 * rb + 2)) * NN);
        const float4* r3 = (const float4*)(WRt + (size_t)(warp + 8 * (4 * rb + 3)) * NN);
        #pragma unroll
        for (int j = 0; j < 4; j++) {
            const int idx  = lane + 32 * j;
            const int base = 4 * idx;
            float4 w0 = r0[idx];
            float4 w1 = r1[idx];
            float4 w2 = r2[idx];
            float4 w3 = r3[idx];
            float u0 = sv_tm1[base + 0], u1 = sv_tm1[base + 1];
            float u2 = sv_tm1[base + 2], u3 = sv_tm1[base + 3];
            float t0 = sv_t[base + 0],   t1 = sv_t[base + 1];
            float t2 = sv_t[base + 2],   t3 = sv_t[base + 3];
            a1[0] = fmaf(w0.x,u0,fmaf(w0.y,u1,fmaf(w0.z,u2,fmaf(w0.w,u3,a1[0]))));
            a1[1] = fmaf(w1.x,u0,fmaf(w1.y,u1,fmaf(w1.z,u2,fmaf(w1.w,u3,a1[1]))));
            a1[2] = fmaf(w2.x,u0,fmaf(w2.y,u1,fmaf(w2.z,u2,fmaf(w2.w,u3,a1[2]))));
            a1[3] = fmaf(w3.x,u0,fmaf(w3.y,u1,fmaf(w3.z,u2,fmaf(w3.w,u3,a1[3]))));
            a2[0] = fmaf(w0.x,t0,fmaf(w0.y,t1,fmaf(w0.z,t2,fmaf(w0.w,t3,a2[0]))));
            a2[1] = fmaf(w1.x,t0,fmaf(w1.y,t1,fmaf(w1.z,t2,fmaf(w1.w,t3,a2[1]))));
            a2[2] = fmaf(w2.x,t0,fmaf(w2.y,t1,fmaf(w2.z,t2,fmaf(w2.w,t3,a2[2]))));
            a2[3] = fmaf(w3.x,t0,fmaf(w3.y,t1,fmaf(w3.z,t2,fmaf(w3.w,t3,a2[3]))));
        }
        // ILP-overlapped butterfly across 8 independent partials
        #pragma unroll
        for (int o = 16; o > 0; o >>= 1) {
            #pragma unroll
            for (int r = 0; r < 4; r++) {
                a1[r] += __shfl_xor_sync(0xFFFFFFFFu, a1[r], o);
                a2[r] += __shfl_xor_sync(0xFFFFFFFFu, a2[r], o);
            }
        }
        if (lane == 0) {
            #pragma unroll
            for (int r = 0; r < 4; r++) {
                sWRx[warp + 8 * (4 * rb + r)] = a1[r];
                sWx [warp + 8 * (4 * rb + r)] = a2[r];
            }
        }
    }
    __syncthreads();

    // ---- Phase B: WLWRx[n]=WL[n,:]·WRx ; vpre[n]=WL[n,:]·Wx ----
    // 16 groups of 16 lanes; group g owns rows n = g + 16*m, m=0..31,
    // unrolled 4 rows per pass (MLP 4 per group, 8 per warp).
    {
        const int g  = tid >> 4;      // 0..15
        const int hl = tid & 15;      // lane in group
        float4 s1 = ((const float4*)sWRx)[hl];
        float4 s2 = ((const float4*)sWx)[hl];
        #pragma unroll
        for (int mo = 0; mo < 8; mo++) {
            const int n0 = g + 16 * (4 * mo);
            float4 w0 = ((const float4*)(WLt + (size_t)(n0 +  0) * KK))[hl];
            float4 w1 = ((const float4*)(WLt + (size_t)(n0 + 16) * KK))[hl];
            float4 w2 = ((const float4*)(WLt + (size_t)(n0 + 32) * KK))[hl];
            float4 w3 = ((const float4*)(WLt + (size_t)(n0 + 48) * KK))[hl];
            float a1_0 = w0.x*s1.x + w0.y*s1.y + w0.z*s1.z + w0.w*s1.w;
            float a1_1 = w1.x*s1.x + w1.y*s1.y + w1.z*s1.z + w1.w*s1.w;
            float a1_2 = w2.x*s1.x + w2.y*s1.y + w2.z*s1.z + w2.w*s1.w;
            float a1_3 = w3.x*s1.x + w3.y*s1.y + w3.z*s1.z + w3.w*s1.w;
            float a2_0 = w0.x*s2.x + w0.y*s2.y + w0.z*s2.z + w0.w*s2.w;
            float a2_1 = w1.x*s2.x + w1.y*s2.y + w1.z*s2.z + w1.w*s2.w;
            float a2_2 = w2.x*s2.x + w2.y*s2.y + w2.z*s2.z + w2.w*s2.w;
            float a2_3 = w3.x*s2.x + w3.y*s2.y + w3.z*s2.z + w3.w*s2.w;
            #pragma unroll
            for (int o = 8; o > 0; o >>= 1) {
                a1_0 += __shfl_xor_sync(0xFFFFFFFFu, a1_0, o);
                a1_1 += __shfl_xor_sync(0xFFFFFFFFu, a1_1, o);
                a1_2 += __shfl_xor_sync(0xFFFFFFFFu, a1_2, o);
                a1_3 += __shfl_xor_sync(0xFFFFFFFFu, a1_3, o);
                a2_0 += __shfl_xor_sync(0xFFFFFFFFu, a2_0, o);
                a2_1 += __shfl_xor_sync(0xFFFFFFFFu, a2_1, o);
                a2_2 += __shfl_xor_sync(0xFFFFFFFFu, a2_2, o);
                a2_3 += __shfl_xor_sync(0xFFFFFFFFu, a2_3, o);
            }
            if (hl == 0) {
                sAcc1[n0 +  0] = a1_0;  sAcc2[n0 +  0] = a2_0;
                sAcc1[n0 + 16] = a1_1;  sAcc2[n0 + 16] = a2_1;
                sAcc1[n0 + 32] = a1_2;  sAcc2[n0 + 32] = a2_2;
                sAcc1[n0 + 48] = a1_3;  sAcc2[n0 + 48] = a2_3;
            }
        }
    }
    __syncthreads();

    // ---- Final vectorized writes: threads 0-127 -> dWL, 128-255 -> v_next ----
    if (tid < 128) {
        float4 o;
        if (msk) {
            float4 a = ((const float4*)sAcc1)[tid];
            float4 t = ((const float4*)sv_t)[tid];
            o.x = G_CONST * t.x - a.x;
            o.y = G_CONST * t.y - a.y;
            o.z = G_CONST * t.z - a.z;
            o.w = G_CONST * t.w - a.w;
        } else {
            o = make_float4(0.f, 0.f, 0.f, 0.f);
        }
        ((float4*)dWLrow)[tid] = o;
    } else if (sel) {
        const int i = tid - 128;
        float4 a = ((const float4*)sAcc2)[i];
        float4 o;
        o.x = tanhf(a.x); o.y = tanhf(a.y);
        o.z = tanhf(a.z); o.w = tanhf(a.w);
        ((float4*)(out_vnext + (size_t)b * NN))[i] = o;
    }
}

extern "C" void kernel_launch(void* const* d_in, const int* in_sizes, int n_in,
                              void* d_out, int out_size) {
    const float* WL    = (const float*)d_in[0];
    const float* WR    = (const float*)d_in[1];
    const float* v_tm1 = (const float*)d_in[2];
    const float* v_t   = (const float*)d_in[3];
    const int*   ac    = (const int*)d_in[4];
    const int*   pcm   = (const int*)d_in[5];
    float* out = (float*)d_out;

    dim3 grid(BB, PP);
    ghu_kernel<<<grid, THREADS>>>(WL, WR, v_tm1, v_t, ac, pcm, out);
}